// round 2
// baseline (speedup 1.0000x reference)
#include <cuda_runtime.h>
#include <math.h>

#define N1CAP 50000
#define E1CAP 1000000
#define N2CAP 256
#define E2CAP 4096
#define FDIM 128
#define ODIM 64
#define BGR 10
#define KSEL 50
#define NN2 199
#define PAD 132

// ---------------- scratch (device globals; no allocation allowed) ----------------
__device__ int   g_deg1[N1CAP], g_wpos1[N1CAP], g_rowptr1[N1CAP + 1];
__device__ int   g_col1[E1CAP];
__device__ int   g_deg2[N2CAP], g_wpos2[N2CAP], g_rowptr2[N2CAP + 1];
__device__ int   g_col2[E2CAP];
__device__ float g_mean1[(size_t)N1CAP * FDIM];
__device__ float g_h1[(size_t)N1CAP * FDIM];
__device__ float g_o1[(size_t)N1CAP * ODIM];
__device__ float g_mean2[N2CAP * FDIM];
__device__ float g_h2[N2CAP * FDIM];
__device__ float g_o2[N2CAP * ODIM];
__device__ float g_lastcol[N1CAP];
__device__ int   g_topk[BGR * KSEL];
__device__ float g_feat[BGR * KSEL * NN2];
__device__ float g_z1[BGR * FDIM];
__device__ float g_y1[BGR * FDIM];

__device__ __forceinline__ float dot4(float4 a, float4 b) {
    return a.x * b.x + a.y * b.y + a.z * b.z + a.w * b.w;
}

// ---------------- CSR build ----------------
__global__ void zero_counts_kernel(int n1, int n2) {
    int i = blockIdx.x * blockDim.x + threadIdx.x;
    if (i < n1) { g_deg1[i] = 0; g_wpos1[i] = 0; }
    if (i < n2) { g_deg2[i] = 0; g_wpos2[i] = 0; }
}

__global__ void degree_kernel(const int* __restrict__ ei, int E, int* __restrict__ deg) {
    int e = blockIdx.x * blockDim.x + threadIdx.x;
    if (e < E) atomicAdd(&deg[ei[E + e]], 1);
}

// single-block exclusive scan (n <= ~50001)
__global__ void scan_kernel(const int* __restrict__ deg, int* __restrict__ rowptr, int n) {
    __shared__ int part[1024];
    int t = threadIdx.x;
    int chunk = (n + 1023) >> 10;
    int s = t * chunk;
    int e = min(s + chunk, n);
    int sum = 0;
    for (int i = s; i < e; i++) sum += deg[i];
    part[t] = sum;
    __syncthreads();
    for (int off = 1; off < 1024; off <<= 1) {
        int v = (t >= off) ? part[t - off] : 0;
        __syncthreads();
        part[t] += v;
        __syncthreads();
    }
    int run = (t == 0) ? 0 : part[t - 1];
    for (int i = s; i < e; i++) { rowptr[i] = run; run += deg[i]; }
    if (t == 1023) rowptr[n] = part[1023];
}

__global__ void scatter_kernel(const int* __restrict__ ei, int E,
                               const int* __restrict__ rowptr, int* __restrict__ wpos,
                               int* __restrict__ col) {
    int e = blockIdx.x * blockDim.x + threadIdx.x;
    if (e >= E) return;
    int d = ei[E + e];
    int p = atomicAdd(&wpos[d], 1);
    col[rowptr[d] + p] = ei[e];
}

// ---------------- mean aggregation: warp per node, float4 lanes ----------------
__global__ void aggregate_kernel(const float* __restrict__ x, const int* __restrict__ rowptr,
                                 const int* __restrict__ col, float* __restrict__ out, int n) {
    int w = (blockIdx.x * blockDim.x + threadIdx.x) >> 5;
    int lane = threadIdx.x & 31;
    if (w >= n) return;
    int s = rowptr[w], e = rowptr[w + 1];
    const float4* x4 = (const float4*)x;
    float4 acc = make_float4(0.f, 0.f, 0.f, 0.f);
    #pragma unroll 4
    for (int j = s; j < e; j++) {
        float4 v = x4[(long long)col[j] * 32 + lane];
        acc.x += v.x; acc.y += v.y; acc.z += v.z; acc.w += v.w;
    }
    float inv = 1.0f / (float)max(e - s, 1);
    acc.x *= inv; acc.y *= inv; acc.z *= inv; acc.w *= inv;
    ((float4*)out)[(long long)w * 32 + lane] = acc;
}

// ---------------- out = relu(mean @ wl^T + bl + x @ wr^T), OUT=128 ----------------
// 128 threads (thread = output), weights in smem (pad 132 -> conflict-free f4 reads),
// 4 nodes register-blocked to amortize weight LDS.
__global__ void linear128_kernel(const float* __restrict__ mean, const float* __restrict__ xin,
                                 const float* __restrict__ wl, const float* __restrict__ bl,
                                 const float* __restrict__ wr, float* __restrict__ out, int n) {
    extern __shared__ unsigned char smraw[];
    float* sm = (float*)smraw;
    float* wlP = sm;                  // 128*PAD
    float* wrP = sm + 128 * PAD;      // 128*PAD
    float* rm = sm + 2 * 128 * PAD;   // 4*128
    float* rx = rm + 4 * 128;         // 4*128
    int t = threadIdx.x;
    for (int idx = t; idx < 128 * 128; idx += 128) {
        int o = idx >> 7, f = idx & 127;
        wlP[o * PAD + f] = wl[idx];
        wrP[o * PAD + f] = wr[idx];
    }
    __syncthreads();
    float bias = bl[t];
    const float4* wl4 = (const float4*)(wlP + t * PAD);
    const float4* wr4 = (const float4*)(wrP + t * PAD);
    for (int base = blockIdx.x * 4; base < n; base += gridDim.x * 4) {
        for (int i = t; i < 4 * 128; i += 128) {
            long long gi = (long long)base * 128 + i;
            bool ok = gi < (long long)n * 128;
            rm[i] = ok ? mean[gi] : 0.f;
            rx[i] = ok ? xin[gi] : 0.f;
        }
        __syncthreads();
        float a0 = bias, a1 = bias, a2 = bias, a3 = bias;
        const float4* rm4 = (const float4*)rm;
        const float4* rx4 = (const float4*)rx;
        #pragma unroll 8
        for (int f4 = 0; f4 < 32; f4++) {
            float4 wlv = wl4[f4], wrv = wr4[f4];
            float4 m, xv;
            m = rm4[f4];      xv = rx4[f4];      a0 += dot4(m, wlv) + dot4(xv, wrv);
            m = rm4[32 + f4]; xv = rx4[32 + f4]; a1 += dot4(m, wlv) + dot4(xv, wrv);
            m = rm4[64 + f4]; xv = rx4[64 + f4]; a2 += dot4(m, wlv) + dot4(xv, wrv);
            m = rm4[96 + f4]; xv = rx4[96 + f4]; a3 += dot4(m, wlv) + dot4(xv, wrv);
        }
        if (base < n)     out[(long long)base * 128 + t]       = fmaxf(a0, 0.f);
        if (base + 1 < n) out[(long long)(base + 1) * 128 + t] = fmaxf(a1, 0.f);
        if (base + 2 < n) out[(long long)(base + 2) * 128 + t] = fmaxf(a2, 0.f);
        if (base + 3 < n) out[(long long)(base + 3) * 128 + t] = fmaxf(a3, 0.f);
        __syncthreads();
    }
}

// ---------------- OUT=64 variant: 128 threads = 64 outputs x 2 f-halves ----------------
__global__ void linear64_kernel(const float* __restrict__ mean, const float* __restrict__ xin,
                                const float* __restrict__ wl, const float* __restrict__ bl,
                                const float* __restrict__ wr, float* __restrict__ out, int n) {
    extern __shared__ unsigned char smraw[];
    float* sm = (float*)smraw;
    float* wlP = sm;                 // 64*PAD
    float* wrP = sm + 64 * PAD;      // 64*PAD
    float* rm = sm + 2 * 64 * PAD;   // 512
    float* rx = rm + 512;            // 512
    float* part = rx + 512;          // 512
    int t = threadIdx.x;
    for (int idx = t; idx < 64 * 128; idx += 128) {
        int o = idx >> 7, f = idx & 127;
        wlP[o * PAD + f] = wl[idx];
        wrP[o * PAD + f] = wr[idx];
    }
    __syncthreads();
    int o = t & 63, half = t >> 6;
    const float4* wl4 = (const float4*)(wlP + o * PAD) + half * 16;
    const float4* wr4 = (const float4*)(wrP + o * PAD) + half * 16;
    for (int base = blockIdx.x * 4; base < n; base += gridDim.x * 4) {
        for (int i = t; i < 512; i += 128) {
            long long gi = (long long)base * 128 + i;
            bool ok = gi < (long long)n * 128;
            rm[i] = ok ? mean[gi] : 0.f;
            rx[i] = ok ? xin[gi] : 0.f;
        }
        __syncthreads();
        float a0 = 0.f, a1 = 0.f, a2 = 0.f, a3 = 0.f;
        const float4* rm4 = (const float4*)rm + half * 16;
        const float4* rx4 = (const float4*)rx + half * 16;
        #pragma unroll 4
        for (int f4 = 0; f4 < 16; f4++) {
            float4 wlv = wl4[f4], wrv = wr4[f4];
            float4 m, xv;
            m = rm4[f4];      xv = rx4[f4];      a0 += dot4(m, wlv) + dot4(xv, wrv);
            m = rm4[32 + f4]; xv = rx4[32 + f4]; a1 += dot4(m, wlv) + dot4(xv, wrv);
            m = rm4[64 + f4]; xv = rx4[64 + f4]; a2 += dot4(m, wlv) + dot4(xv, wrv);
            m = rm4[96 + f4]; xv = rx4[96 + f4]; a3 += dot4(m, wlv) + dot4(xv, wrv);
        }
        part[t * 4 + 0] = a0; part[t * 4 + 1] = a1;
        part[t * 4 + 2] = a2; part[t * 4 + 3] = a3;
        __syncthreads();
        if (t < 64) {
            float b = bl[t];
            #pragma unroll
            for (int nb = 0; nb < 4; nb++) {
                if (base + nb < n) {
                    float r = b + part[t * 4 + nb] + part[(t + 64) * 4 + nb];
                    out[(long long)(base + nb) * 64 + t] = fmaxf(r, 0.f);
                }
            }
        }
        __syncthreads();
    }
}

// ---------------- last dist column (vs out2 row n2-1) ----------------
__global__ void lastcol_kernel(const float* __restrict__ o1, const float* __restrict__ o2,
                               float* __restrict__ lastc, int n, int n2) {
    __shared__ float b[64];
    if (threadIdx.x < 64) b[threadIdx.x] = o2[(n2 - 1) * 64 + threadIdx.x];
    __syncthreads();
    int w = (blockIdx.x * blockDim.x + threadIdx.x) >> 5;
    int lane = threadIdx.x & 31;
    if (w >= n) return;
    float t0 = o1[(long long)w * 64 + lane] - b[lane];
    float t1 = o1[(long long)w * 64 + 32 + lane] - b[32 + lane];
    float d = t0 * t0 + t1 * t1;
    for (int off = 16; off; off >>= 1) d += __shfl_xor_sync(0xffffffffu, d, off);
    if (lane == 0) lastc[w] = sqrtf(fmaxf(d, 0.f));
}

// ---------------- per-graph top-K via bitonic sort of 64-bit keys ----------------
// key encodes (value desc, index asc) to match stable argsort(-x)
__global__ void topk_kernel(const float* __restrict__ lastc, int* __restrict__ topk, int npg) {
    extern __shared__ unsigned char smraw[];
    unsigned long long* key = (unsigned long long*)smraw;
    const int NS = 8192;
    int g = blockIdx.x;
    for (int i = threadIdx.x; i < NS; i += blockDim.x) {
        unsigned long long k;
        if (i < npg) {
            unsigned u = __float_as_uint(lastc[g * npg + i]);
            u = (u & 0x80000000u) ? ~u : (u | 0x80000000u);  // order-preserving
            u = ~u;                                          // descending value
            k = ((unsigned long long)u << 32) | (unsigned)i; // asc index tie-break
        } else {
            k = 0xFFFFFFFFFFFFFFFFull;
        }
        key[i] = k;
    }
    __syncthreads();
    for (int size = 2; size <= NS; size <<= 1) {
        for (int stride = size >> 1; stride > 0; stride >>= 1) {
            for (int i = threadIdx.x; i < NS; i += blockDim.x) {
                int j = i ^ stride;
                if (j > i) {
                    unsigned long long a = key[i], b = key[j];
                    bool up = ((i & size) == 0);
                    if ((a > b) == up) { key[i] = b; key[j] = a; }
                }
            }
            __syncthreads();
        }
    }
    if (threadIdx.x < KSEL)
        topk[g * KSEL + threadIdx.x] = g * npg + (int)(key[threadIdx.x] & 0xFFFFFFFFull);
}

// ---------------- full dist rows only for the B*K selected nodes ----------------
__global__ void feat_kernel(const float* __restrict__ o1, const float* __restrict__ o2,
                            const int* __restrict__ topk, float* __restrict__ feat, int n2) {
    __shared__ float a[64];
    int s = blockIdx.x;
    int node = topk[s];
    if (threadIdx.x < 64) a[threadIdx.x] = o1[(long long)node * 64 + threadIdx.x];
    __syncthreads();
    for (int j = threadIdx.x; j < n2; j += blockDim.x) {
        float d = 0.f;
        #pragma unroll
        for (int f = 0; f < 64; f++) {
            float t = a[f] - o2[j * 64 + f];
            d += t * t;
        }
        feat[s * n2 + j] = sqrtf(fmaxf(d, 0.f));
    }
}

// ---------------- fc1: z[b][o] = feat[b] . w[o] + bias ----------------
__global__ void fc1_kernel(const float* __restrict__ feat, const float* __restrict__ w,
                           const float* __restrict__ bias, float* __restrict__ z, int indim) {
    int b = blockIdx.x >> 7, o = blockIdx.x & 127;
    const float* fr = feat + (long long)b * indim;
    const float* wr = w + (long long)o * indim;
    float acc = 0.f;
    for (int i = threadIdx.x; i < indim; i += blockDim.x) acc += fr[i] * wr[i];
    __shared__ float red[256];
    red[threadIdx.x] = acc;
    __syncthreads();
    for (int s = 128; s > 0; s >>= 1) {
        if (threadIdx.x < s) red[threadIdx.x] += red[threadIdx.x + s];
        __syncthreads();
    }
    if (threadIdx.x == 0) z[b * 128 + o] = red[0] + bias[o];
}

// ---------------- layernorm (2-pass) + relu, F threads per row ----------------
__global__ void ln_relu_kernel(const float* __restrict__ z, const float* __restrict__ g,
                               const float* __restrict__ b, float* __restrict__ y, int F) {
    int bb = blockIdx.x, t = threadIdx.x;
    __shared__ float s[128];
    float v = z[bb * F + t];
    s[t] = v;
    __syncthreads();
    for (int st = F >> 1; st > 0; st >>= 1) { if (t < st) s[t] += s[t + st]; __syncthreads(); }
    float mu = s[0] / (float)F;
    __syncthreads();
    float d = v - mu;
    s[t] = d * d;
    __syncthreads();
    for (int st = F >> 1; st > 0; st >>= 1) { if (t < st) s[t] += s[t + st]; __syncthreads(); }
    float var = s[0] / (float)F;
    y[bb * F + t] = fmaxf(d * rsqrtf(var + 1e-5f) * g[t] + b[t], 0.f);
}

// ---------------- fc2 + LN + relu + fc3 + sigmoid ----------------
__global__ void head_kernel(const float* __restrict__ y1, const float* __restrict__ w2,
                            const float* __restrict__ b2, const float* __restrict__ g2,
                            const float* __restrict__ bn2, const float* __restrict__ w3,
                            const float* __restrict__ b3, float* __restrict__ out) {
    int b = blockIdx.x, t = threadIdx.x;  // 64 threads
    __shared__ float yr[128];
    yr[t] = y1[b * 128 + t];
    yr[64 + t] = y1[b * 128 + 64 + t];
    __syncthreads();
    float acc = b2[t];
    #pragma unroll 4
    for (int f = 0; f < 128; f++) acc += yr[f] * w2[t * 128 + f];
    __shared__ float s1[64], s2[64];
    s1[t] = acc;
    __syncthreads();
    for (int s = 32; s > 0; s >>= 1) { if (t < s) s1[t] += s1[t + s]; __syncthreads(); }
    float mu = s1[0] / 64.f;
    __syncthreads();
    float d = acc - mu;
    s2[t] = d * d;
    __syncthreads();
    for (int s = 32; s > 0; s >>= 1) { if (t < s) s2[t] += s2[t + s]; __syncthreads(); }
    float var = s2[0] / 64.f;
    float v = fmaxf(d * rsqrtf(var + 1e-5f) * g2[t] + bn2[t], 0.f);
    __syncthreads();
    s1[t] = v * w3[t];
    __syncthreads();
    for (int s = 32; s > 0; s >>= 1) { if (t < s) s1[t] += s1[t + s]; __syncthreads(); }
    if (t == 0) out[b] = 1.f / (1.f + expf(-(s1[0] + b3[0])));
}

// ---------------- launch ----------------
extern "C" void kernel_launch(void* const* d_in, const int* in_sizes, int n_in,
                              void* d_out, int out_size) {
    const float* x1   = (const float*)d_in[0];
    const int*   ei1  = (const int*)d_in[1];
    const float* x2   = (const float*)d_in[3];
    const int*   ei2  = (const int*)d_in[4];
    const float* w1l  = (const float*)d_in[5];
    const float* b1l  = (const float*)d_in[6];
    const float* w1r  = (const float*)d_in[7];
    const float* w2l  = (const float*)d_in[8];
    const float* b2l  = (const float*)d_in[9];
    const float* w2r  = (const float*)d_in[10];
    const float* fc1w = (const float*)d_in[11];
    const float* fc1b = (const float*)d_in[12];
    const float* ln1g = (const float*)d_in[13];
    const float* ln1b = (const float*)d_in[14];
    const float* fc2w = (const float*)d_in[15];
    const float* fc2b = (const float*)d_in[16];
    const float* ln2g = (const float*)d_in[17];
    const float* ln2b = (const float*)d_in[18];
    const float* fc3w = (const float*)d_in[19];
    const float* fc3b = (const float*)d_in[20];
    float* out = (float*)d_out;

    int N1 = in_sizes[0] / FDIM;
    int E1 = in_sizes[1] / 2;
    int N2 = in_sizes[3] / FDIM;
    int E2 = in_sizes[4] / 2;
    int NPG = N1 / BGR;
    int INDIM = KSEL * N2;

    int *deg1, *wpos1, *rowptr1, *col1, *deg2, *wpos2, *rowptr2, *col2, *topk;
    float *mean1, *h1, *o1, *mean2, *h2, *o2, *lastc, *feat, *z1, *y1;
    cudaGetSymbolAddress((void**)&deg1, g_deg1);
    cudaGetSymbolAddress((void**)&wpos1, g_wpos1);
    cudaGetSymbolAddress((void**)&rowptr1, g_rowptr1);
    cudaGetSymbolAddress((void**)&col1, g_col1);
    cudaGetSymbolAddress((void**)&deg2, g_deg2);
    cudaGetSymbolAddress((void**)&wpos2, g_wpos2);
    cudaGetSymbolAddress((void**)&rowptr2, g_rowptr2);
    cudaGetSymbolAddress((void**)&col2, g_col2);
    cudaGetSymbolAddress((void**)&topk, g_topk);
    cudaGetSymbolAddress((void**)&mean1, g_mean1);
    cudaGetSymbolAddress((void**)&h1, g_h1);
    cudaGetSymbolAddress((void**)&o1, g_o1);
    cudaGetSymbolAddress((void**)&mean2, g_mean2);
    cudaGetSymbolAddress((void**)&h2, g_h2);
    cudaGetSymbolAddress((void**)&o2, g_o2);
    cudaGetSymbolAddress((void**)&lastc, g_lastcol);
    cudaGetSymbolAddress((void**)&feat, g_feat);
    cudaGetSymbolAddress((void**)&z1, g_z1);
    cudaGetSymbolAddress((void**)&y1, g_y1);

    const int SM128 = (2 * 128 * PAD + 8 * 128) * 4;       // 139264
    const int SM64  = (2 * 64 * PAD + 3 * 512) * 4;        // 73728
    cudaFuncSetAttribute(linear128_kernel, cudaFuncAttributeMaxDynamicSharedMemorySize, SM128);
    cudaFuncSetAttribute(linear64_kernel, cudaFuncAttributeMaxDynamicSharedMemorySize, SM64);
    cudaFuncSetAttribute(topk_kernel, cudaFuncAttributeMaxDynamicSharedMemorySize, 65536);

    int zmax = (N1 > N2 ? N1 : N2);
    zero_counts_kernel<<<(zmax + 255) / 256, 256>>>(N1, N2);
    degree_kernel<<<(E1 + 255) / 256, 256>>>(ei1, E1, deg1);
    degree_kernel<<<(E2 + 255) / 256, 256>>>(ei2, E2, deg2);
    scan_kernel<<<1, 1024>>>(deg1, rowptr1, N1);
    scan_kernel<<<1, 1024>>>(deg2, rowptr2, N2);
    scatter_kernel<<<(E1 + 255) / 256, 256>>>(ei1, E1, rowptr1, wpos1, col1);
    scatter_kernel<<<(E2 + 255) / 256, 256>>>(ei2, E2, rowptr2, wpos2, col2);

    // graph1 GNN
    aggregate_kernel<<<(N1 * 32 + 255) / 256, 256>>>(x1, rowptr1, col1, mean1, N1);
    linear128_kernel<<<740, 128, SM128>>>(mean1, x1, w1l, b1l, w1r, h1, N1);
    aggregate_kernel<<<(N1 * 32 + 255) / 256, 256>>>(h1, rowptr1, col1, mean1, N1);
    linear64_kernel<<<740, 128, SM64>>>(mean1, h1, w2l, b2l, w2r, o1, N1);

    // graph2 GNN (tiny)
    aggregate_kernel<<<(N2 * 32 + 255) / 256, 256>>>(x2, rowptr2, col2, mean2, N2);
    linear128_kernel<<<50, 128, SM128>>>(mean2, x2, w1l, b1l, w1r, h2, N2);
    aggregate_kernel<<<(N2 * 32 + 255) / 256, 256>>>(h2, rowptr2, col2, mean2, N2);
    linear64_kernel<<<50, 128, SM64>>>(mean2, h2, w2l, b2l, w2r, o2, N2);

    // ranking + selected features
    lastcol_kernel<<<(N1 * 32 + 255) / 256, 256>>>(o1, o2, lastc, N1, N2);
    topk_kernel<<<BGR, 1024, 65536>>>(lastc, topk, NPG);
    feat_kernel<<<BGR * KSEL, 256>>>(o1, o2, topk, feat, N2);

    // MLP head
    fc1_kernel<<<BGR * 128, 256>>>(feat, fc1w, fc1b, z1, INDIM);
    ln_relu_kernel<<<BGR, 128>>>(z1, ln1g, ln1b, y1, 128);
    head_kernel<<<BGR, 64>>>(y1, fc2w, fc2b, ln2g, ln2b, fc3w, fc3b, out);
}

// round 3
// speedup vs baseline: 1.4780x; 1.4780x over previous
#include <cuda_runtime.h>
#include <math.h>

#define N1CAP 50000
#define E1CAP 1000000
#define N2CAP 256
#define E2CAP 4096
#define FDIM 128
#define ODIM 64
#define BGR 10
#define KSEL 50
#define NN2 199
#define PAD 132
#define NB 8

// ---------------- scratch (device globals; no allocation allowed) ----------------
__device__ int   g_deg1[N1CAP], g_wpos1[N1CAP], g_rowptr1[N1CAP + 1];
__device__ int   g_col1[E1CAP];
__device__ int   g_deg2[N2CAP], g_wpos2[N2CAP], g_rowptr2[N2CAP + 1];
__device__ int   g_col2[E2CAP];
__device__ int   g_part1[128], g_part2[128];
__device__ float g_mean1[(size_t)N1CAP * FDIM];
__device__ float g_h1[(size_t)N1CAP * FDIM];
__device__ float g_o1[(size_t)N1CAP * ODIM];
__device__ float g_mean2[N2CAP * FDIM];
__device__ float g_h2[N2CAP * FDIM];
__device__ float g_o2[N2CAP * ODIM];
__device__ float g_lastcol[N1CAP];
__device__ int   g_topk[BGR * KSEL];
__device__ float g_feat[BGR * KSEL * NN2];
__device__ float g_z1[BGR * FDIM];
__device__ float g_y1[BGR * FDIM];

__device__ __forceinline__ float dot4(float4 a, float4 b) {
    return a.x * b.x + a.y * b.y + a.z * b.z + a.w * b.w;
}

// ---------------- CSR build ----------------
__global__ void zero_counts_kernel(int n1, int n2) {
    int i = blockIdx.x * blockDim.x + threadIdx.x;
    if (i < n1) { g_deg1[i] = 0; g_wpos1[i] = 0; }
    if (i < n2) { g_deg2[i] = 0; g_wpos2[i] = 0; }
}

__global__ void degree_kernel(const int* __restrict__ ei, int E, int* __restrict__ deg) {
    int e = blockIdx.x * blockDim.x + threadIdx.x;
    if (e < E) atomicAdd(&deg[ei[E + e]], 1);
}

// phase 1: per-block (1024-chunk) sums
__global__ void block_sum_kernel(const int* __restrict__ deg, int n, int* __restrict__ part) {
    __shared__ int s[256];
    int b = blockIdx.x;
    int base = b * 1024;
    int sum = 0;
    for (int i = threadIdx.x; i < 1024; i += 256) {
        int gi = base + i;
        if (gi < n) sum += deg[gi];
    }
    s[threadIdx.x] = sum;
    __syncthreads();
    for (int st = 128; st > 0; st >>= 1) {
        if (threadIdx.x < st) s[threadIdx.x] += s[threadIdx.x + st];
        __syncthreads();
    }
    if (threadIdx.x == 0) part[b] = s[0];
}

// phase 2: single-block exclusive scan of partials (nb <= 128); writes rowptr[n]=total
__global__ void scan_part_kernel(int* __restrict__ part, int nb, int* __restrict__ rowptr, int n) {
    __shared__ int s[128];
    int t = threadIdx.x;
    int v = (t < nb) ? part[t] : 0;
    s[t] = v;
    __syncthreads();
    for (int off = 1; off < 128; off <<= 1) {
        int u = (t >= off) ? s[t - off] : 0;
        __syncthreads();
        s[t] += u;
        __syncthreads();
    }
    if (t < nb) part[t] = s[t] - v;   // exclusive
    if (t == 127) rowptr[n] = s[127]; // total
}

// phase 3: per-block scan of its 1024-chunk + offset
__global__ void write_rowptr_kernel(const int* __restrict__ deg, int n,
                                    const int* __restrict__ part, int* __restrict__ rowptr) {
    __shared__ int s[1024];
    int b = blockIdx.x, t = threadIdx.x;
    int gi = b * 1024 + t;
    int v = (gi < n) ? deg[gi] : 0;
    s[t] = v;
    __syncthreads();
    for (int off = 1; off < 1024; off <<= 1) {
        int u = (t >= off) ? s[t - off] : 0;
        __syncthreads();
        s[t] += u;
        __syncthreads();
    }
    if (gi < n) rowptr[gi] = part[b] + s[t] - v;
}

__global__ void scatter_kernel(const int* __restrict__ ei, int E,
                               const int* __restrict__ rowptr, int* __restrict__ wpos,
                               int* __restrict__ col) {
    int e = blockIdx.x * blockDim.x + threadIdx.x;
    if (e >= E) return;
    int d = ei[E + e];
    int p = atomicAdd(&wpos[d], 1);
    col[rowptr[d] + p] = ei[e];
}

// ---------------- mean aggregation: warp per node, float4 lanes ----------------
__global__ void aggregate_kernel(const float* __restrict__ x, const int* __restrict__ rowptr,
                                 const int* __restrict__ col, float* __restrict__ out, int n) {
    int w = (blockIdx.x * blockDim.x + threadIdx.x) >> 5;
    int lane = threadIdx.x & 31;
    if (w >= n) return;
    int s = rowptr[w], e = rowptr[w + 1];
    const float4* x4 = (const float4*)x;
    float4 acc = make_float4(0.f, 0.f, 0.f, 0.f);
    #pragma unroll 4
    for (int j = s; j < e; j++) {
        float4 v = x4[(long long)col[j] * 32 + lane];
        acc.x += v.x; acc.y += v.y; acc.z += v.z; acc.w += v.w;
    }
    float inv = 1.0f / (float)max(e - s, 1);
    acc.x *= inv; acc.y *= inv; acc.z *= inv; acc.w *= inv;
    ((float4*)out)[(long long)w * 32 + lane] = acc;
}

// ---------------- out = relu(mean @ wl^T + bl + x @ wr^T), OUT=128 ----------------
// 512 threads = 4 teams x 128 outputs; 8-node register blocking; persistent grid.
__global__ void __launch_bounds__(512, 1)
linear128_kernel(const float* __restrict__ mean, const float* __restrict__ xin,
                 const float* __restrict__ wl, const float* __restrict__ bl,
                 const float* __restrict__ wr, float* __restrict__ out, int n) {
    extern __shared__ unsigned char smraw[];
    float* sm = (float*)smraw;
    float* wlP = sm;                  // 128*PAD
    float* wrP = sm + 128 * PAD;      // 128*PAD
    float* data = sm + 2 * 128 * PAD; // 4 teams * (NB*128 mean + NB*128 x)
    int t = threadIdx.x;
    for (int idx = t; idx < 128 * 128; idx += 512) {
        int o = idx >> 7, f = idx & 127;
        wlP[o * PAD + f] = wl[idx];
        wrP[o * PAD + f] = wr[idx];
    }
    __syncthreads();
    int tm = t >> 7, o = t & 127;
    float bias = bl[o];
    const float4* wl4 = (const float4*)(wlP + o * PAD);
    const float4* wr4 = (const float4*)(wrP + o * PAD);
    float* my_rm = data + tm * (NB * 128 * 2);
    float* my_rx = my_rm + NB * 128;
    int ngroups = (n + NB - 1) / NB;
    for (int g0 = blockIdx.x * 4; g0 < ngroups; g0 += gridDim.x * 4) {
        for (int idx = t; idx < 4 * NB * 128; idx += 512) {
            int tt = idx >> 10;          // /(NB*128)
            int loc = idx & 1023;
            long long gnode = (long long)(g0 + tt) * NB + (loc >> 7);
            int f = loc & 127;
            bool ok = gnode < n;
            float* dst = data + tt * (NB * 128 * 2);
            long long gi = gnode * 128 + f;
            dst[loc] = ok ? mean[gi] : 0.f;
            dst[NB * 128 + loc] = ok ? xin[gi] : 0.f;
        }
        __syncthreads();
        float acc[NB];
        #pragma unroll
        for (int i = 0; i < NB; i++) acc[i] = bias;
        const float4* rm4 = (const float4*)my_rm;
        const float4* rx4 = (const float4*)my_rx;
        #pragma unroll 4
        for (int f4 = 0; f4 < 32; f4++) {
            float4 wlv = wl4[f4], wrv = wr4[f4];
            #pragma unroll
            for (int nb = 0; nb < NB; nb++)
                acc[nb] += dot4(rm4[nb * 32 + f4], wlv) + dot4(rx4[nb * 32 + f4], wrv);
        }
        long long base = (long long)(g0 + tm) * NB;
        #pragma unroll
        for (int nb = 0; nb < NB; nb++) {
            long long gn = base + nb;
            if (gn < n) out[gn * 128 + o] = fmaxf(acc[nb], 0.f);
        }
        __syncthreads();
    }
}

// ---------------- OUT=64 variant: 512 threads = 8 teams x 64 outputs ----------------
__global__ void __launch_bounds__(512, 1)
linear64_kernel(const float* __restrict__ mean, const float* __restrict__ xin,
                const float* __restrict__ wl, const float* __restrict__ bl,
                const float* __restrict__ wr, float* __restrict__ out, int n) {
    extern __shared__ unsigned char smraw[];
    float* sm = (float*)smraw;
    float* wlP = sm;                 // 64*PAD
    float* wrP = sm + 64 * PAD;      // 64*PAD
    float* data = sm + 2 * 64 * PAD; // 8 teams * (NB*128 mean + NB*128 x)
    int t = threadIdx.x;
    for (int idx = t; idx < 64 * 128; idx += 512) {
        int o = idx >> 7, f = idx & 127;
        wlP[o * PAD + f] = wl[idx];
        wrP[o * PAD + f] = wr[idx];
    }
    __syncthreads();
    int tm = t >> 6, o = t & 63;
    float bias = bl[o];
    const float4* wl4 = (const float4*)(wlP + o * PAD);
    const float4* wr4 = (const float4*)(wrP + o * PAD);
    float* my_rm = data + tm * (NB * 128 * 2);
    float* my_rx = my_rm + NB * 128;
    int ngroups = (n + NB - 1) / NB;
    for (int g0 = blockIdx.x * 8; g0 < ngroups; g0 += gridDim.x * 8) {
        for (int idx = t; idx < 8 * NB * 128; idx += 512) {
            int tt = idx >> 10;
            int loc = idx & 1023;
            long long gnode = (long long)(g0 + tt) * NB + (loc >> 7);
            int f = loc & 127;
            bool ok = gnode < n;
            float* dst = data + tt * (NB * 128 * 2);
            long long gi = gnode * 128 + f;
            dst[loc] = ok ? mean[gi] : 0.f;
            dst[NB * 128 + loc] = ok ? xin[gi] : 0.f;
        }
        __syncthreads();
        float acc[NB];
        #pragma unroll
        for (int i = 0; i < NB; i++) acc[i] = bias;
        const float4* rm4 = (const float4*)my_rm;
        const float4* rx4 = (const float4*)my_rx;
        #pragma unroll 4
        for (int f4 = 0; f4 < 32; f4++) {
            float4 wlv = wl4[f4], wrv = wr4[f4];
            #pragma unroll
            for (int nb = 0; nb < NB; nb++)
                acc[nb] += dot4(rm4[nb * 32 + f4], wlv) + dot4(rx4[nb * 32 + f4], wrv);
        }
        long long base = (long long)(g0 + tm) * NB;
        #pragma unroll
        for (int nb = 0; nb < NB; nb++) {
            long long gn = base + nb;
            if (gn < n) out[gn * 64 + o] = fmaxf(acc[nb], 0.f);
        }
        __syncthreads();
    }
}

// ---------------- last dist column (vs out2 row n2-1) ----------------
__global__ void lastcol_kernel(const float* __restrict__ o1, const float* __restrict__ o2,
                               float* __restrict__ lastc, int n, int n2) {
    __shared__ float b[64];
    if (threadIdx.x < 64) b[threadIdx.x] = o2[(n2 - 1) * 64 + threadIdx.x];
    __syncthreads();
    int w = (blockIdx.x * blockDim.x + threadIdx.x) >> 5;
    int lane = threadIdx.x & 31;
    if (w >= n) return;
    float t0 = o1[(long long)w * 64 + lane] - b[lane];
    float t1 = o1[(long long)w * 64 + 32 + lane] - b[32 + lane];
    float d = t0 * t0 + t1 * t1;
    for (int off = 16; off; off >>= 1) d += __shfl_xor_sync(0xffffffffu, d, off);
    if (lane == 0) lastc[w] = sqrtf(fmaxf(d, 0.f));
}

// ---------------- per-graph top-K via bitonic sort of 64-bit keys ----------------
__global__ void topk_kernel(const float* __restrict__ lastc, int* __restrict__ topk, int npg) {
    extern __shared__ unsigned char smraw[];
    unsigned long long* key = (unsigned long long*)smraw;
    const int NS = 8192;
    int g = blockIdx.x;
    for (int i = threadIdx.x; i < NS; i += blockDim.x) {
        unsigned long long k;
        if (i < npg) {
            unsigned u = __float_as_uint(lastc[g * npg + i]);
            u = (u & 0x80000000u) ? ~u : (u | 0x80000000u);
            u = ~u;
            k = ((unsigned long long)u << 32) | (unsigned)i;
        } else {
            k = 0xFFFFFFFFFFFFFFFFull;
        }
        key[i] = k;
    }
    __syncthreads();
    for (int size = 2; size <= NS; size <<= 1) {
        for (int stride = size >> 1; stride > 0; stride >>= 1) {
            for (int i = threadIdx.x; i < NS; i += blockDim.x) {
                int j = i ^ stride;
                if (j > i) {
                    unsigned long long a = key[i], b = key[j];
                    bool up = ((i & size) == 0);
                    if ((a > b) == up) { key[i] = b; key[j] = a; }
                }
            }
            __syncthreads();
        }
    }
    if (threadIdx.x < KSEL)
        topk[g * KSEL + threadIdx.x] = g * npg + (int)(key[threadIdx.x] & 0xFFFFFFFFull);
}

// ---------------- full dist rows only for the B*K selected nodes ----------------
__global__ void feat_kernel(const float* __restrict__ o1, const float* __restrict__ o2,
                            const int* __restrict__ topk, float* __restrict__ feat, int n2) {
    __shared__ float a[64];
    int s = blockIdx.x;
    int node = topk[s];
    if (threadIdx.x < 64) a[threadIdx.x] = o1[(long long)node * 64 + threadIdx.x];
    __syncthreads();
    for (int j = threadIdx.x; j < n2; j += blockDim.x) {
        float d = 0.f;
        #pragma unroll
        for (int f = 0; f < 64; f++) {
            float t = a[f] - o2[j * 64 + f];
            d += t * t;
        }
        feat[s * n2 + j] = sqrtf(fmaxf(d, 0.f));
    }
}

// ---------------- fc1 ----------------
__global__ void fc1_kernel(const float* __restrict__ feat, const float* __restrict__ w,
                           const float* __restrict__ bias, float* __restrict__ z, int indim) {
    int b = blockIdx.x >> 7, o = blockIdx.x & 127;
    const float* fr = feat + (long long)b * indim;
    const float* wr = w + (long long)o * indim;
    float acc = 0.f;
    for (int i = threadIdx.x; i < indim; i += blockDim.x) acc += fr[i] * wr[i];
    __shared__ float red[256];
    red[threadIdx.x] = acc;
    __syncthreads();
    for (int s = 128; s > 0; s >>= 1) {
        if (threadIdx.x < s) red[threadIdx.x] += red[threadIdx.x + s];
        __syncthreads();
    }
    if (threadIdx.x == 0) z[b * 128 + o] = red[0] + bias[o];
}

// ---------------- layernorm + relu ----------------
__global__ void ln_relu_kernel(const float* __restrict__ z, const float* __restrict__ g,
                               const float* __restrict__ b, float* __restrict__ y, int F) {
    int bb = blockIdx.x, t = threadIdx.x;
    __shared__ float s[128];
    float v = z[bb * F + t];
    s[t] = v;
    __syncthreads();
    for (int st = F >> 1; st > 0; st >>= 1) { if (t < st) s[t] += s[t + st]; __syncthreads(); }
    float mu = s[0] / (float)F;
    __syncthreads();
    float d = v - mu;
    s[t] = d * d;
    __syncthreads();
    for (int st = F >> 1; st > 0; st >>= 1) { if (t < st) s[t] += s[t + st]; __syncthreads(); }
    float var = s[0] / (float)F;
    y[bb * F + t] = fmaxf(d * rsqrtf(var + 1e-5f) * g[t] + b[t], 0.f);
}

// ---------------- fc2 + LN + relu + fc3 + sigmoid ----------------
__global__ void head_kernel(const float* __restrict__ y1, const float* __restrict__ w2,
                            const float* __restrict__ b2, const float* __restrict__ g2,
                            const float* __restrict__ bn2, const float* __restrict__ w3,
                            const float* __restrict__ b3, float* __restrict__ out) {
    int b = blockIdx.x, t = threadIdx.x;  // 64 threads
    __shared__ float yr[128];
    yr[t] = y1[b * 128 + t];
    yr[64 + t] = y1[b * 128 + 64 + t];
    __syncthreads();
    float acc = b2[t];
    #pragma unroll 4
    for (int f = 0; f < 128; f++) acc += yr[f] * w2[t * 128 + f];
    __shared__ float s1[64], s2[64];
    s1[t] = acc;
    __syncthreads();
    for (int s = 32; s > 0; s >>= 1) { if (t < s) s1[t] += s1[t + s]; __syncthreads(); }
    float mu = s1[0] / 64.f;
    __syncthreads();
    float d = acc - mu;
    s2[t] = d * d;
    __syncthreads();
    for (int s = 32; s > 0; s >>= 1) { if (t < s) s2[t] += s2[t + s]; __syncthreads(); }
    float var = s2[0] / 64.f;
    float v = fmaxf(d * rsqrtf(var + 1e-5f) * g2[t] + bn2[t], 0.f);
    __syncthreads();
    s1[t] = v * w3[t];
    __syncthreads();
    for (int s = 32; s > 0; s >>= 1) { if (t < s) s1[t] += s1[t + s]; __syncthreads(); }
    if (t == 0) out[b] = 1.f / (1.f + expf(-(s1[0] + b3[0])));
}

// ---------------- launch ----------------
extern "C" void kernel_launch(void* const* d_in, const int* in_sizes, int n_in,
                              void* d_out, int out_size) {
    const float* x1   = (const float*)d_in[0];
    const int*   ei1  = (const int*)d_in[1];
    const float* x2   = (const float*)d_in[3];
    const int*   ei2  = (const int*)d_in[4];
    const float* w1l  = (const float*)d_in[5];
    const float* b1l  = (const float*)d_in[6];
    const float* w1r  = (const float*)d_in[7];
    const float* w2l  = (const float*)d_in[8];
    const float* b2l  = (const float*)d_in[9];
    const float* w2r  = (const float*)d_in[10];
    const float* fc1w = (const float*)d_in[11];
    const float* fc1b = (const float*)d_in[12];
    const float* ln1g = (const float*)d_in[13];
    const float* ln1b = (const float*)d_in[14];
    const float* fc2w = (const float*)d_in[15];
    const float* fc2b = (const float*)d_in[16];
    const float* ln2g = (const float*)d_in[17];
    const float* ln2b = (const float*)d_in[18];
    const float* fc3w = (const float*)d_in[19];
    const float* fc3b = (const float*)d_in[20];
    float* out = (float*)d_out;

    int N1 = in_sizes[0] / FDIM;
    int E1 = in_sizes[1] / 2;
    int N2 = in_sizes[3] / FDIM;
    int E2 = in_sizes[4] / 2;
    int NPG = N1 / BGR;
    int INDIM = KSEL * N2;

    int *deg1, *wpos1, *rowptr1, *col1, *deg2, *wpos2, *rowptr2, *col2, *topk, *part1, *part2;
    float *mean1, *h1, *o1, *mean2, *h2, *o2, *lastc, *feat, *z1, *y1;
    cudaGetSymbolAddress((void**)&deg1, g_deg1);
    cudaGetSymbolAddress((void**)&wpos1, g_wpos1);
    cudaGetSymbolAddress((void**)&rowptr1, g_rowptr1);
    cudaGetSymbolAddress((void**)&col1, g_col1);
    cudaGetSymbolAddress((void**)&deg2, g_deg2);
    cudaGetSymbolAddress((void**)&wpos2, g_wpos2);
    cudaGetSymbolAddress((void**)&rowptr2, g_rowptr2);
    cudaGetSymbolAddress((void**)&col2, g_col2);
    cudaGetSymbolAddress((void**)&part1, g_part1);
    cudaGetSymbolAddress((void**)&part2, g_part2);
    cudaGetSymbolAddress((void**)&topk, g_topk);
    cudaGetSymbolAddress((void**)&mean1, g_mean1);
    cudaGetSymbolAddress((void**)&h1, g_h1);
    cudaGetSymbolAddress((void**)&o1, g_o1);
    cudaGetSymbolAddress((void**)&mean2, g_mean2);
    cudaGetSymbolAddress((void**)&h2, g_h2);
    cudaGetSymbolAddress((void**)&o2, g_o2);
    cudaGetSymbolAddress((void**)&lastc, g_lastcol);
    cudaGetSymbolAddress((void**)&feat, g_feat);
    cudaGetSymbolAddress((void**)&z1, g_z1);
    cudaGetSymbolAddress((void**)&y1, g_y1);

    const int SM128 = (2 * 128 * PAD + 4 * NB * 128 * 2) * 4;  // 167936
    const int SM64  = (2 * 64 * PAD + 8 * NB * 128 * 2) * 4;   // 133120
    cudaFuncSetAttribute(linear128_kernel, cudaFuncAttributeMaxDynamicSharedMemorySize, SM128);
    cudaFuncSetAttribute(linear64_kernel, cudaFuncAttributeMaxDynamicSharedMemorySize, SM64);
    cudaFuncSetAttribute(topk_kernel, cudaFuncAttributeMaxDynamicSharedMemorySize, 65536);

    int zmax = (N1 > N2 ? N1 : N2);
    int nb1 = (N1 + 1023) / 1024, nb2 = (N2 + 1023) / 1024;
    zero_counts_kernel<<<(zmax + 255) / 256, 256>>>(N1, N2);
    degree_kernel<<<(E1 + 255) / 256, 256>>>(ei1, E1, deg1);
    degree_kernel<<<(E2 + 255) / 256, 256>>>(ei2, E2, deg2);
    block_sum_kernel<<<nb1, 256>>>(deg1, N1, part1);
    block_sum_kernel<<<nb2, 256>>>(deg2, N2, part2);
    scan_part_kernel<<<1, 128>>>(part1, nb1, rowptr1, N1);
    scan_part_kernel<<<1, 128>>>(part2, nb2, rowptr2, N2);
    write_rowptr_kernel<<<nb1, 1024>>>(deg1, N1, part1, rowptr1);
    write_rowptr_kernel<<<nb2, 1024>>>(deg2, N2, part2, rowptr2);
    scatter_kernel<<<(E1 + 255) / 256, 256>>>(ei1, E1, rowptr1, wpos1, col1);
    scatter_kernel<<<(E2 + 255) / 256, 256>>>(ei2, E2, rowptr2, wpos2, col2);

    // graph1 GNN
    aggregate_kernel<<<(N1 * 32 + 255) / 256, 256>>>(x1, rowptr1, col1, mean1, N1);
    linear128_kernel<<<148, 512, SM128>>>(mean1, x1, w1l, b1l, w1r, h1, N1);
    aggregate_kernel<<<(N1 * 32 + 255) / 256, 256>>>(h1, rowptr1, col1, mean1, N1);
    linear64_kernel<<<148, 512, SM64>>>(mean1, h1, w2l, b2l, w2r, o1, N1);

    // graph2 GNN (tiny)
    aggregate_kernel<<<(N2 * 32 + 255) / 256, 256>>>(x2, rowptr2, col2, mean2, N2);
    linear128_kernel<<<7, 512, SM128>>>(mean2, x2, w1l, b1l, w1r, h2, N2);
    aggregate_kernel<<<(N2 * 32 + 255) / 256, 256>>>(h2, rowptr2, col2, mean2, N2);
    linear64_kernel<<<4, 512, SM64>>>(mean2, h2, w2l, b2l, w2r, o2, N2);

    // ranking + selected features
    lastcol_kernel<<<(N1 * 32 + 255) / 256, 256>>>(o1, o2, lastc, N1, N2);
    topk_kernel<<<BGR, 1024, 65536>>>(lastc, topk, NPG);
    feat_kernel<<<BGR * KSEL, 256>>>(o1, o2, topk, feat, N2);

    // MLP head
    fc1_kernel<<<BGR * 128, 256>>>(feat, fc1w, fc1b, z1, INDIM);
    ln_relu_kernel<<<BGR, 128>>>(z1, ln1g, ln1b, y1, 128);
    head_kernel<<<BGR, 64>>>(y1, fc2w, fc2b, ln2g, ln2b, fc3w, fc3b, out);
}

// round 4
// speedup vs baseline: 1.9924x; 1.3480x over previous
#include <cuda_runtime.h>
#include <math.h>

#define N1CAP 50000
#define E1CAP 1000000
#define N2CAP 256
#define E2CAP 4096
#define FDIM 128
#define ODIM 64
#define BGR 10
#define KSEL 50
#define NN2 199
#define PAD 132
#define NB 8

typedef unsigned long long u64;

// ---------------- scratch (device globals; no allocation allowed) ----------------
__device__ int   g_deg1[N1CAP], g_wpos1[N1CAP], g_rowptr1[N1CAP + 1];
__device__ int   g_col1[E1CAP];
__device__ int   g_deg2[N2CAP], g_wpos2[N2CAP], g_rowptr2[N2CAP + 1];
__device__ int   g_col2[E2CAP];
__device__ int   g_part1[128], g_part2[128];
__device__ float g_mean1[(size_t)N1CAP * FDIM];
__device__ float g_h1[(size_t)N1CAP * FDIM];
__device__ float g_o1[(size_t)N1CAP * ODIM];
__device__ float g_mean2[N2CAP * FDIM];
__device__ float g_h2[N2CAP * FDIM];
__device__ float g_o2[N2CAP * ODIM];
__device__ float g_lastcol[N1CAP];
__device__ u64   g_pk[BGR * 8 * KSEL];
__device__ int   g_topk[BGR * KSEL];
__device__ float g_feat[BGR * KSEL * NN2];
__device__ float g_z1[BGR * FDIM];
__device__ float g_y1[BGR * FDIM];

__device__ __forceinline__ void ffma2(u64& d, u64 a, u64 b) {
    asm("fma.rn.f32x2 %0, %1, %2, %0;" : "+l"(d) : "l"(a), "l"(b));
}
__device__ __forceinline__ float2 u2f(u64 v) {
    float2 r; asm("mov.b64 {%0, %1}, %2;" : "=f"(r.x), "=f"(r.y) : "l"(v)); return r;
}

// ---------------- CSR build ----------------
__global__ void zero_counts_kernel(int n1, int n2) {
    int i = blockIdx.x * blockDim.x + threadIdx.x;
    if (i < n1) { g_deg1[i] = 0; g_wpos1[i] = 0; }
    if (i < n2) { g_deg2[i] = 0; g_wpos2[i] = 0; }
}

__global__ void degree_kernel(const int* __restrict__ ei, int E, int* __restrict__ deg) {
    int e = blockIdx.x * blockDim.x + threadIdx.x;
    if (e < E) atomicAdd(&deg[ei[E + e]], 1);
}

__global__ void block_sum_kernel(const int* __restrict__ deg, int n, int* __restrict__ part) {
    __shared__ int s[256];
    int b = blockIdx.x;
    int base = b * 1024;
    int sum = 0;
    for (int i = threadIdx.x; i < 1024; i += 256) {
        int gi = base + i;
        if (gi < n) sum += deg[gi];
    }
    s[threadIdx.x] = sum;
    __syncthreads();
    for (int st = 128; st > 0; st >>= 1) {
        if (threadIdx.x < st) s[threadIdx.x] += s[threadIdx.x + st];
        __syncthreads();
    }
    if (threadIdx.x == 0) part[b] = s[0];
}

__global__ void scan_part_kernel(int* __restrict__ part, int nb, int* __restrict__ rowptr, int n) {
    __shared__ int s[128];
    int t = threadIdx.x;
    int v = (t < nb) ? part[t] : 0;
    s[t] = v;
    __syncthreads();
    for (int off = 1; off < 128; off <<= 1) {
        int u = (t >= off) ? s[t - off] : 0;
        __syncthreads();
        s[t] += u;
        __syncthreads();
    }
    if (t < nb) part[t] = s[t] - v;
    if (t == 127) rowptr[n] = s[127];
}

__global__ void write_rowptr_kernel(const int* __restrict__ deg, int n,
                                    const int* __restrict__ part, int* __restrict__ rowptr) {
    __shared__ int s[1024];
    int b = blockIdx.x, t = threadIdx.x;
    int gi = b * 1024 + t;
    int v = (gi < n) ? deg[gi] : 0;
    s[t] = v;
    __syncthreads();
    for (int off = 1; off < 1024; off <<= 1) {
        int u = (t >= off) ? s[t - off] : 0;
        __syncthreads();
        s[t] += u;
        __syncthreads();
    }
    if (gi < n) rowptr[gi] = part[b] + s[t] - v;
}

__global__ void scatter_kernel(const int* __restrict__ ei, int E,
                               const int* __restrict__ rowptr, int* __restrict__ wpos,
                               int* __restrict__ col) {
    int e = blockIdx.x * blockDim.x + threadIdx.x;
    if (e >= E) return;
    int d = ei[E + e];
    int p = atomicAdd(&wpos[d], 1);
    col[rowptr[d] + p] = ei[e];
}

// ---------------- mean aggregation: warp per node, float4 lanes ----------------
__global__ void aggregate_kernel(const float* __restrict__ x, const int* __restrict__ rowptr,
                                 const int* __restrict__ col, float* __restrict__ out, int n) {
    int w = (blockIdx.x * blockDim.x + threadIdx.x) >> 5;
    int lane = threadIdx.x & 31;
    if (w >= n) return;
    int s = rowptr[w], e = rowptr[w + 1];
    const float4* x4 = (const float4*)x;
    float4 acc = make_float4(0.f, 0.f, 0.f, 0.f);
    #pragma unroll 4
    for (int j = s; j < e; j++) {
        float4 v = x4[(long long)col[j] * 32 + lane];
        acc.x += v.x; acc.y += v.y; acc.z += v.z; acc.w += v.w;
    }
    float inv = 1.0f / (float)max(e - s, 1);
    acc.x *= inv; acc.y *= inv; acc.z *= inv; acc.w *= inv;
    ((float4*)out)[(long long)w * 32 + lane] = acc;
}

// ---------------- out = relu(mean @ wl^T + bl + x @ wr^T), OUT=128 ----------------
// 512 threads = 8 teams x 64 threads; thread computes outputs o and o+64 (OB=2);
// NB=8 node register blocking; FFMA2 (fp32x2) inner product; persistent grid.
__global__ void __launch_bounds__(512, 1)
linear128_kernel(const float* __restrict__ mean, const float* __restrict__ xin,
                 const float* __restrict__ wl, const float* __restrict__ bl,
                 const float* __restrict__ wr, float* __restrict__ out, int n) {
    extern __shared__ unsigned char smraw[];
    float* sm = (float*)smraw;
    float* wlP = sm;                  // 128*PAD
    float* wrP = sm + 128 * PAD;      // 128*PAD
    float* data = sm + 2 * 128 * PAD; // 8 teams * (NB*128 mean + NB*128 x)
    int t = threadIdx.x;
    for (int idx = t; idx < 128 * 128; idx += 512) {
        int o = idx >> 7, f = idx & 127;
        wlP[o * PAD + f] = wl[idx];
        wrP[o * PAD + f] = wr[idx];
    }
    __syncthreads();
    int tm = t >> 6, o = t & 63;
    float biasL = bl[o], biasH = bl[o + 64];
    const ulonglong2* wlL = (const ulonglong2*)(wlP + o * PAD);
    const ulonglong2* wlH = (const ulonglong2*)(wlP + (o + 64) * PAD);
    const ulonglong2* wrL = (const ulonglong2*)(wrP + o * PAD);
    const ulonglong2* wrH = (const ulonglong2*)(wrP + (o + 64) * PAD);
    const ulonglong2* rm2 = (const ulonglong2*)(data + tm * (NB * 128 * 2));
    const ulonglong2* rx2 = rm2 + NB * 32;
    const float4* mean4 = (const float4*)mean;
    const float4* xin4 = (const float4*)xin;
    int ngroups = (n + NB - 1) / NB;
    for (int g0 = blockIdx.x * 8; g0 < ngroups; g0 += gridDim.x * 8) {
        // stage 8 teams * NB nodes * 32 float4 per array
        for (int idx = t; idx < 2048; idx += 512) {
            int tt = idx >> 8;
            int loc = idx & 255;
            long long node = (long long)(g0 + tt) * NB + (loc >> 5);
            int f4i = loc & 31;
            float4 z = make_float4(0.f, 0.f, 0.f, 0.f);
            float4* dm = (float4*)(data + tt * (NB * 128 * 2));
            float4* dx = dm + NB * 32;
            bool ok = node < n;
            dm[loc] = ok ? mean4[node * 32 + f4i] : z;
            dx[loc] = ok ? xin4[node * 32 + f4i] : z;
        }
        __syncthreads();
        u64 accL[NB], accH[NB];
        #pragma unroll
        for (int i = 0; i < NB; i++) { accL[i] = 0ull; accH[i] = 0ull; }
        #pragma unroll 4
        for (int f4 = 0; f4 < 32; f4++) {
            ulonglong2 a0 = wlL[f4], a1 = wlH[f4];
            ulonglong2 b0 = wrL[f4], b1 = wrH[f4];
            #pragma unroll
            for (int nb = 0; nb < NB; nb++) {
                ulonglong2 m = rm2[nb * 32 + f4];
                ulonglong2 xv = rx2[nb * 32 + f4];
                ffma2(accL[nb], a0.x, m.x); ffma2(accL[nb], a0.y, m.y);
                ffma2(accL[nb], b0.x, xv.x); ffma2(accL[nb], b0.y, xv.y);
                ffma2(accH[nb], a1.x, m.x); ffma2(accH[nb], a1.y, m.y);
                ffma2(accH[nb], b1.x, xv.x); ffma2(accH[nb], b1.y, xv.y);
            }
        }
        long long base = (long long)(g0 + tm) * NB;
        #pragma unroll
        for (int nb = 0; nb < NB; nb++) {
            long long gn = base + nb;
            if (gn < n) {
                float2 l = u2f(accL[nb]);
                float2 h = u2f(accH[nb]);
                out[gn * 128 + o]      = fmaxf(l.x + l.y + biasL, 0.f);
                out[gn * 128 + o + 64] = fmaxf(h.x + h.y + biasH, 0.f);
            }
        }
        __syncthreads();
    }
}

// ---------------- OUT=64 variant: 16 teams x 32 threads; outputs o and o+32 ----------------
__global__ void __launch_bounds__(512, 1)
linear64_kernel(const float* __restrict__ mean, const float* __restrict__ xin,
                const float* __restrict__ wl, const float* __restrict__ bl,
                const float* __restrict__ wr, float* __restrict__ out, int n) {
    extern __shared__ unsigned char smraw[];
    float* sm = (float*)smraw;
    float* wlP = sm;                 // 64*PAD
    float* wrP = sm + 64 * PAD;      // 64*PAD
    float* data = sm + 2 * 64 * PAD; // 16 teams * (NB*128 mean + NB*128 x)
    int t = threadIdx.x;
    for (int idx = t; idx < 64 * 128; idx += 512) {
        int o = idx >> 7, f = idx & 127;
        wlP[o * PAD + f] = wl[idx];
        wrP[o * PAD + f] = wr[idx];
    }
    __syncthreads();
    int tm = t >> 5, o = t & 31;
    float biasL = bl[o], biasH = bl[o + 32];
    const ulonglong2* wlL = (const ulonglong2*)(wlP + o * PAD);
    const ulonglong2* wlH = (const ulonglong2*)(wlP + (o + 32) * PAD);
    const ulonglong2* wrL = (const ulonglong2*)(wrP + o * PAD);
    const ulonglong2* wrH = (const ulonglong2*)(wrP + (o + 32) * PAD);
    const ulonglong2* rm2 = (const ulonglong2*)(data + tm * (NB * 128 * 2));
    const ulonglong2* rx2 = rm2 + NB * 32;
    const float4* mean4 = (const float4*)mean;
    const float4* xin4 = (const float4*)xin;
    int ngroups = (n + NB - 1) / NB;
    for (int g0 = blockIdx.x * 16; g0 < ngroups; g0 += gridDim.x * 16) {
        for (int idx = t; idx < 4096; idx += 512) {
            int tt = idx >> 8;
            int loc = idx & 255;
            long long node = (long long)(g0 + tt) * NB + (loc >> 5);
            int f4i = loc & 31;
            float4 z = make_float4(0.f, 0.f, 0.f, 0.f);
            float4* dm = (float4*)(data + tt * (NB * 128 * 2));
            float4* dx = dm + NB * 32;
            bool ok = node < n;
            dm[loc] = ok ? mean4[node * 32 + f4i] : z;
            dx[loc] = ok ? xin4[node * 32 + f4i] : z;
        }
        __syncthreads();
        u64 accL[NB], accH[NB];
        #pragma unroll
        for (int i = 0; i < NB; i++) { accL[i] = 0ull; accH[i] = 0ull; }
        #pragma unroll 4
        for (int f4 = 0; f4 < 32; f4++) {
            ulonglong2 a0 = wlL[f4], a1 = wlH[f4];
            ulonglong2 b0 = wrL[f4], b1 = wrH[f4];
            #pragma unroll
            for (int nb = 0; nb < NB; nb++) {
                ulonglong2 m = rm2[nb * 32 + f4];
                ulonglong2 xv = rx2[nb * 32 + f4];
                ffma2(accL[nb], a0.x, m.x); ffma2(accL[nb], a0.y, m.y);
                ffma2(accL[nb], b0.x, xv.x); ffma2(accL[nb], b0.y, xv.y);
                ffma2(accH[nb], a1.x, m.x); ffma2(accH[nb], a1.y, m.y);
                ffma2(accH[nb], b1.x, xv.x); ffma2(accH[nb], b1.y, xv.y);
            }
        }
        long long base = (long long)(g0 + tm) * NB;
        #pragma unroll
        for (int nb = 0; nb < NB; nb++) {
            long long gn = base + nb;
            if (gn < n) {
                float2 l = u2f(accL[nb]);
                float2 h = u2f(accH[nb]);
                out[gn * 64 + o]      = fmaxf(l.x + l.y + biasL, 0.f);
                out[gn * 64 + o + 32] = fmaxf(h.x + h.y + biasH, 0.f);
            }
        }
        __syncthreads();
    }
}

// ---------------- last dist column (vs out2 row n2-1) ----------------
__global__ void lastcol_kernel(const float* __restrict__ o1, const float* __restrict__ o2,
                               float* __restrict__ lastc, int n, int n2) {
    __shared__ float b[64];
    if (threadIdx.x < 64) b[threadIdx.x] = o2[(n2 - 1) * 64 + threadIdx.x];
    __syncthreads();
    int w = (blockIdx.x * blockDim.x + threadIdx.x) >> 5;
    int lane = threadIdx.x & 31;
    if (w >= n) return;
    float t0 = o1[(long long)w * 64 + lane] - b[lane];
    float t1 = o1[(long long)w * 64 + 32 + lane] - b[32 + lane];
    float d = t0 * t0 + t1 * t1;
    for (int off = 16; off; off >>= 1) d += __shfl_xor_sync(0xffffffffu, d, off);
    if (lane == 0) lastc[w] = sqrtf(fmaxf(d, 0.f));
}

// ---------------- top-K: per-chunk bitonic (exact), then merge ----------------
__global__ void topk_part_kernel(const float* __restrict__ lastc, u64* __restrict__ pk,
                                 int npg, int ch) {
    __shared__ u64 key[1024];
    int g = blockIdx.x >> 3, c = blockIdx.x & 7;
    int base = c * ch;
    for (int i = threadIdx.x; i < 1024; i += blockDim.x) {
        int li = base + i;
        u64 k = 0xFFFFFFFFFFFFFFFFull;
        if (i < ch && li < npg) {
            unsigned u = __float_as_uint(lastc[g * npg + li]);
            u = (u & 0x80000000u) ? ~u : (u | 0x80000000u);
            u = ~u;
            k = ((u64)u << 32) | (unsigned)li;
        }
        key[i] = k;
    }
    __syncthreads();
    for (int size = 2; size <= 1024; size <<= 1) {
        for (int stride = size >> 1; stride > 0; stride >>= 1) {
            for (int i = threadIdx.x; i < 1024; i += blockDim.x) {
                int j = i ^ stride;
                if (j > i) {
                    u64 a = key[i], b = key[j];
                    bool up = ((i & size) == 0);
                    if ((a > b) == up) { key[i] = b; key[j] = a; }
                }
            }
            __syncthreads();
        }
    }
    if (threadIdx.x < KSEL) pk[(g * 8 + c) * KSEL + threadIdx.x] = key[threadIdx.x];
}

__global__ void topk_merge_kernel(const u64* __restrict__ pk, int* __restrict__ topk, int npg) {
    __shared__ u64 key[512];
    int g = blockIdx.x;
    for (int i = threadIdx.x; i < 512; i += blockDim.x)
        key[i] = (i < 8 * KSEL) ? pk[g * 8 * KSEL + i] : 0xFFFFFFFFFFFFFFFFull;
    __syncthreads();
    for (int size = 2; size <= 512; size <<= 1) {
        for (int stride = size >> 1; stride > 0; stride >>= 1) {
            for (int i = threadIdx.x; i < 512; i += blockDim.x) {
                int j = i ^ stride;
                if (j > i) {
                    u64 a = key[i], b = key[j];
                    bool up = ((i & size) == 0);
                    if ((a > b) == up) { key[i] = b; key[j] = a; }
                }
            }
            __syncthreads();
        }
    }
    if (threadIdx.x < KSEL)
        topk[g * KSEL + threadIdx.x] = g * npg + (int)(key[threadIdx.x] & 0xFFFFFFFFull);
}

// ---------------- full dist rows only for the B*K selected nodes ----------------
__global__ void feat_kernel(const float* __restrict__ o1, const float* __restrict__ o2,
                            const int* __restrict__ topk, float* __restrict__ feat, int n2) {
    __shared__ float a[64];
    int s = blockIdx.x;
    int node = topk[s];
    if (threadIdx.x < 64) a[threadIdx.x] = o1[(long long)node * 64 + threadIdx.x];
    __syncthreads();
    for (int j = threadIdx.x; j < n2; j += blockDim.x) {
        float d = 0.f;
        #pragma unroll
        for (int f = 0; f < 64; f++) {
            float t = a[f] - o2[j * 64 + f];
            d += t * t;
        }
        feat[s * n2 + j] = sqrtf(fmaxf(d, 0.f));
    }
}

// ---------------- fc1 ----------------
__global__ void fc1_kernel(const float* __restrict__ feat, const float* __restrict__ w,
                           const float* __restrict__ bias, float* __restrict__ z, int indim) {
    int b = blockIdx.x >> 7, o = blockIdx.x & 127;
    const float* fr = feat + (long long)b * indim;
    const float* wr = w + (long long)o * indim;
    float acc = 0.f;
    for (int i = threadIdx.x; i < indim; i += blockDim.x) acc += fr[i] * wr[i];
    __shared__ float red[256];
    red[threadIdx.x] = acc;
    __syncthreads();
    for (int s = 128; s > 0; s >>= 1) {
        if (threadIdx.x < s) red[threadIdx.x] += red[threadIdx.x + s];
        __syncthreads();
    }
    if (threadIdx.x == 0) z[b * 128 + o] = red[0] + bias[o];
}

// ---------------- layernorm + relu ----------------
__global__ void ln_relu_kernel(const float* __restrict__ z, const float* __restrict__ g,
                               const float* __restrict__ b, float* __restrict__ y, int F) {
    int bb = blockIdx.x, t = threadIdx.x;
    __shared__ float s[128];
    float v = z[bb * F + t];
    s[t] = v;
    __syncthreads();
    for (int st = F >> 1; st > 0; st >>= 1) { if (t < st) s[t] += s[t + st]; __syncthreads(); }
    float mu = s[0] / (float)F;
    __syncthreads();
    float d = v - mu;
    s[t] = d * d;
    __syncthreads();
    for (int st = F >> 1; st > 0; st >>= 1) { if (t < st) s[t] += s[t + st]; __syncthreads(); }
    float var = s[0] / (float)F;
    y[bb * F + t] = fmaxf(d * rsqrtf(var + 1e-5f) * g[t] + b[t], 0.f);
}

// ---------------- fc2 + LN + relu + fc3 + sigmoid ----------------
__global__ void head_kernel(const float* __restrict__ y1, const float* __restrict__ w2,
                            const float* __restrict__ b2, const float* __restrict__ g2,
                            const float* __restrict__ bn2, const float* __restrict__ w3,
                            const float* __restrict__ b3, float* __restrict__ out) {
    int b = blockIdx.x, t = threadIdx.x;  // 64 threads
    __shared__ float yr[128];
    yr[t] = y1[b * 128 + t];
    yr[64 + t] = y1[b * 128 + 64 + t];
    __syncthreads();
    float acc = b2[t];
    #pragma unroll 4
    for (int f = 0; f < 128; f++) acc += yr[f] * w2[t * 128 + f];
    __shared__ float s1[64], s2[64];
    s1[t] = acc;
    __syncthreads();
    for (int s = 32; s > 0; s >>= 1) { if (t < s) s1[t] += s1[t + s]; __syncthreads(); }
    float mu = s1[0] / 64.f;
    __syncthreads();
    float d = acc - mu;
    s2[t] = d * d;
    __syncthreads();
    for (int s = 32; s > 0; s >>= 1) { if (t < s) s2[t] += s2[t + s]; __syncthreads(); }
    float var = s2[0] / 64.f;
    float v = fmaxf(d * rsqrtf(var + 1e-5f) * g2[t] + bn2[t], 0.f);
    __syncthreads();
    s1[t] = v * w3[t];
    __syncthreads();
    for (int s = 32; s > 0; s >>= 1) { if (t < s) s1[t] += s1[t + s]; __syncthreads(); }
    if (t == 0) out[b] = 1.f / (1.f + expf(-(s1[0] + b3[0])));
}

// ---------------- launch ----------------
extern "C" void kernel_launch(void* const* d_in, const int* in_sizes, int n_in,
                              void* d_out, int out_size) {
    const float* x1   = (const float*)d_in[0];
    const int*   ei1  = (const int*)d_in[1];
    const float* x2   = (const float*)d_in[3];
    const int*   ei2  = (const int*)d_in[4];
    const float* w1l  = (const float*)d_in[5];
    const float* b1l  = (const float*)d_in[6];
    const float* w1r  = (const float*)d_in[7];
    const float* w2l  = (const float*)d_in[8];
    const float* b2l  = (const float*)d_in[9];
    const float* w2r  = (const float*)d_in[10];
    const float* fc1w = (const float*)d_in[11];
    const float* fc1b = (const float*)d_in[12];
    const float* ln1g = (const float*)d_in[13];
    const float* ln1b = (const float*)d_in[14];
    const float* fc2w = (const float*)d_in[15];
    const float* fc2b = (const float*)d_in[16];
    const float* ln2g = (const float*)d_in[17];
    const float* ln2b = (const float*)d_in[18];
    const float* fc3w = (const float*)d_in[19];
    const float* fc3b = (const float*)d_in[20];
    float* out = (float*)d_out;

    int N1 = in_sizes[0] / FDIM;
    int E1 = in_sizes[1] / 2;
    int N2 = in_sizes[3] / FDIM;
    int E2 = in_sizes[4] / 2;
    int NPG = N1 / BGR;
    int INDIM = KSEL * N2;
    int CH = (NPG + 7) / 8;

    int *deg1, *wpos1, *rowptr1, *col1, *deg2, *wpos2, *rowptr2, *col2, *topk, *part1, *part2;
    float *mean1, *h1, *o1, *mean2, *h2, *o2, *lastc, *feat, *z1, *y1;
    u64 *pk;
    cudaGetSymbolAddress((void**)&deg1, g_deg1);
    cudaGetSymbolAddress((void**)&wpos1, g_wpos1);
    cudaGetSymbolAddress((void**)&rowptr1, g_rowptr1);
    cudaGetSymbolAddress((void**)&col1, g_col1);
    cudaGetSymbolAddress((void**)&deg2, g_deg2);
    cudaGetSymbolAddress((void**)&wpos2, g_wpos2);
    cudaGetSymbolAddress((void**)&rowptr2, g_rowptr2);
    cudaGetSymbolAddress((void**)&col2, g_col2);
    cudaGetSymbolAddress((void**)&part1, g_part1);
    cudaGetSymbolAddress((void**)&part2, g_part2);
    cudaGetSymbolAddress((void**)&pk, g_pk);
    cudaGetSymbolAddress((void**)&topk, g_topk);
    cudaGetSymbolAddress((void**)&mean1, g_mean1);
    cudaGetSymbolAddress((void**)&h1, g_h1);
    cudaGetSymbolAddress((void**)&o1, g_o1);
    cudaGetSymbolAddress((void**)&mean2, g_mean2);
    cudaGetSymbolAddress((void**)&h2, g_h2);
    cudaGetSymbolAddress((void**)&o2, g_o2);
    cudaGetSymbolAddress((void**)&lastc, g_lastcol);
    cudaGetSymbolAddress((void**)&feat, g_feat);
    cudaGetSymbolAddress((void**)&z1, g_z1);
    cudaGetSymbolAddress((void**)&y1, g_y1);

    const int SM128 = (2 * 128 * PAD + 8 * NB * 128 * 2) * 4;   // 200704
    const int SM64  = (2 * 64 * PAD + 16 * NB * 128 * 2) * 4;   // 198656
    cudaFuncSetAttribute(linear128_kernel, cudaFuncAttributeMaxDynamicSharedMemorySize, SM128);
    cudaFuncSetAttribute(linear64_kernel, cudaFuncAttributeMaxDynamicSharedMemorySize, SM64);

    int zmax = (N1 > N2 ? N1 : N2);
    int nb1 = (N1 + 1023) / 1024, nb2 = (N2 + 1023) / 1024;
    zero_counts_kernel<<<(zmax + 255) / 256, 256>>>(N1, N2);
    degree_kernel<<<(E1 + 255) / 256, 256>>>(ei1, E1, deg1);
    degree_kernel<<<(E2 + 255) / 256, 256>>>(ei2, E2, deg2);
    block_sum_kernel<<<nb1, 256>>>(deg1, N1, part1);
    block_sum_kernel<<<nb2, 256>>>(deg2, N2, part2);
    scan_part_kernel<<<1, 128>>>(part1, nb1, rowptr1, N1);
    scan_part_kernel<<<1, 128>>>(part2, nb2, rowptr2, N2);
    write_rowptr_kernel<<<nb1, 1024>>>(deg1, N1, part1, rowptr1);
    write_rowptr_kernel<<<nb2, 1024>>>(deg2, N2, part2, rowptr2);
    scatter_kernel<<<(E1 + 255) / 256, 256>>>(ei1, E1, rowptr1, wpos1, col1);
    scatter_kernel<<<(E2 + 255) / 256, 256>>>(ei2, E2, rowptr2, wpos2, col2);

    // graph1 GNN
    aggregate_kernel<<<(N1 * 32 + 255) / 256, 256>>>(x1, rowptr1, col1, mean1, N1);
    linear128_kernel<<<148, 512, SM128>>>(mean1, x1, w1l, b1l, w1r, h1, N1);
    aggregate_kernel<<<(N1 * 32 + 255) / 256, 256>>>(h1, rowptr1, col1, mean1, N1);
    linear64_kernel<<<148, 512, SM64>>>(mean1, h1, w2l, b2l, w2r, o1, N1);

    // graph2 GNN (tiny)
    aggregate_kernel<<<(N2 * 32 + 255) / 256, 256>>>(x2, rowptr2, col2, mean2, N2);
    linear128_kernel<<<4, 512, SM128>>>(mean2, x2, w1l, b1l, w1r, h2, N2);
    aggregate_kernel<<<(N2 * 32 + 255) / 256, 256>>>(h2, rowptr2, col2, mean2, N2);
    linear64_kernel<<<2, 512, SM64>>>(mean2, h2, w2l, b2l, w2r, o2, N2);

    // ranking + selected features
    lastcol_kernel<<<(N1 * 32 + 255) / 256, 256>>>(o1, o2, lastc, N1, N2);
    topk_part_kernel<<<BGR * 8, 512>>>(lastc, pk, NPG, CH);
    topk_merge_kernel<<<BGR, 512>>>(pk, topk, NPG);
    feat_kernel<<<BGR * KSEL, 256>>>(o1, o2, topk, feat, N2);

    // MLP head
    fc1_kernel<<<BGR * 128, 256>>>(feat, fc1w, fc1b, z1, INDIM);
    ln_relu_kernel<<<BGR, 128>>>(z1, ln1g, ln1b, y1, 128);
    head_kernel<<<BGR, 64>>>(y1, fc2w, fc2b, ln2g, ln2b, fc3w, fc3b, out);
}